// round 6
// baseline (speedup 1.0000x reference)
#include <cuda_runtime.h>

#define S_LEN 2048
#define B_SZ  512
#define HID   64
#define NGATE 256
#define ROWS  4
#define NCTA  (B_SZ / ROWS)   // 128
#define NTHR  256

typedef unsigned long long u64;

// Ping-pong sequence buffers for inter-layer hidden states: (S, B, H) fp32.
__device__ float g_seq0[S_LEN * B_SZ * HID];
__device__ float g_seq1[S_LEN * B_SZ * HID];

__device__ __forceinline__ u64 fma2(u64 a, u64 b, u64 c) {
    u64 d;
    asm("fma.rn.f32x2 %0, %1, %2, %3;" : "=l"(d) : "l"(a), "l"(b), "l"(c));
    return d;
}
__device__ __forceinline__ u64 pack2(float lo, float hi) {
    u64 r; asm("mov.b64 %0, {%1, %2};" : "=l"(r) : "f"(lo), "f"(hi)); return r;
}
__device__ __forceinline__ float2 unpack2(u64 v) {
    float2 f; asm("mov.b64 {%0, %1}, %2;" : "=f"(f.x), "=f"(f.y) : "l"(v)); return f;
}

__device__ __forceinline__ float sigm_f(float x) {
    float e = __expf(-x);
    return __fdividef(1.0f, 1.0f + e);
}
__device__ __forceinline__ float tanh_f(float x) {
    float a = fabsf(x);
    float e = __expf(-2.0f * a);
    float t = __fdividef(1.0f - e, 1.0f + e);
    return copysignf(t, x);
}

// SRC: 0 -> g_seq0, 1 -> g_seq1, 2 -> external x (B, S, IN_DIM)
// DST: 0 -> g_seq0, 1 -> g_seq1, 2 -> no sequence output
template <int IN_DIM, int SRC, int DST, bool FINAL>
__global__ __launch_bounds__(NTHR, 1)
void lstm_layer_kernel(const float* __restrict__ x_ext,
                       const float* __restrict__ Wih,
                       const float* __restrict__ Whh,
                       const float* __restrict__ bih,
                       const float* __restrict__ bhh,
                       const float* __restrict__ fc_w,
                       const float* __restrict__ fc_b,
                       float* __restrict__ out_fc)
{
    const int tid = threadIdx.x;
    const int b0  = blockIdx.x * ROWS;

    const float* in_seq  = (SRC == 0) ? g_seq0 : (SRC == 1) ? g_seq1 : x_ext;
    float*       out_seq = (DST == 0) ? g_seq0 : (DST == 1) ? g_seq1 : nullptr;

    __shared__ __align__(16) float h_s[ROWS][HID];
    __shared__ __align__(16) float x_s[2][ROWS][IN_DIM];   // double-buffered
    __shared__ float gates_s[ROWS][NGATE];

    // --- per-thread weights packed as f32x2 pairs in registers (gate g = tid) ---
    constexpr int NWH = HID / 2;       // 32 pairs
    constexpr int NWI = IN_DIM / 2;    // 32 or 2 pairs
    u64 whh2[NWH];
    u64 wih2[NWI];
    {
        const u64* Whh_u = reinterpret_cast<const u64*>(Whh);
        const u64* Wih_u = reinterpret_cast<const u64*>(Wih);
        #pragma unroll
        for (int j = 0; j < NWH; j++) whh2[j] = Whh_u[tid * NWH + j];
        #pragma unroll
        for (int j = 0; j < NWI; j++) wih2[j] = Wih_u[tid * NWI + j];
    }
    const float bsum = bih[tid] + bhh[tid];

    // --- state init ---
    const int urow = tid >> 6, uj = tid & 63;
    h_s[urow][uj] = 0.0f;
    float c_reg = 0.0f;

    // --- input staging map: ROWS*IN_DIM elements, <= 1 per thread ---
    constexpr int XELEM = ROWS * IN_DIM;      // 256 (layers 1/2) or 16 (layer 0)
    const bool xi_act = (tid < XELEM);
    const int  xi_row = tid / IN_DIM;
    const int  xi_k   = tid - xi_row * IN_DIM;

    auto load_x = [&](int t) -> float {
        if (!xi_act) return 0.0f;
        if (SRC == 2) {
            return x_ext[(b0 + xi_row) * (S_LEN * IN_DIM) + t * IN_DIM + xi_k];
        } else {
            return in_seq[t * (B_SZ * HID) + (b0 + xi_row) * HID + xi_k];
        }
    };

    if (xi_act) x_s[0][xi_row][xi_k] = load_x(0);
    __syncthreads();

    for (int t = 0; t < S_LEN; t++) {
        const int par = t & 1;
        // prefetch next input (LDG latency hidden under the gate GEMV)
        float x_next = (t + 1 < S_LEN) ? load_x(t + 1) : 0.0f;

        // --- gate compute: packed f32x2 dot products ---
        u64 acc_h[ROWS], acc_x[ROWS];
        #pragma unroll
        for (int r = 0; r < ROWS; r++) {
            acc_h[r] = pack2(bsum, 0.0f);
            acc_x[r] = pack2(0.0f, 0.0f);
        }

        #pragma unroll
        for (int j = 0; j < NWH; j += 2) {       // pairs j, j+1 = floats 2j..2j+3
            #pragma unroll
            for (int r = 0; r < ROWS; r++) {
                double2 h2 = *reinterpret_cast<const double2*>(&h_s[r][2 * j]);
                acc_h[r] = fma2(whh2[j],     __double_as_longlong(h2.x), acc_h[r]);
                acc_h[r] = fma2(whh2[j + 1], __double_as_longlong(h2.y), acc_h[r]);
                if (IN_DIM == HID) {
                    double2 x2 = *reinterpret_cast<const double2*>(&x_s[par][r][2 * j]);
                    acc_x[r] = fma2(wih2[j],     __double_as_longlong(x2.x), acc_x[r]);
                    acc_x[r] = fma2(wih2[j + 1], __double_as_longlong(x2.y), acc_x[r]);
                }
            }
        }
        if (IN_DIM == 4) {
            #pragma unroll
            for (int r = 0; r < ROWS; r++) {
                double2 x2 = *reinterpret_cast<const double2*>(&x_s[par][r][0]);
                acc_x[r] = fma2(wih2[0], __double_as_longlong(x2.x), acc_x[r]);
                acc_x[r] = fma2(wih2[1], __double_as_longlong(x2.y), acc_x[r]);
            }
        }

        #pragma unroll
        for (int r = 0; r < ROWS; r++) {
            float2 ah = unpack2(acc_h[r]);
            float2 ax = unpack2(acc_x[r]);
            gates_s[r][tid] = (ah.x + ah.y) + (ax.x + ax.y);
        }
        __syncthreads();   // gates ready

        // --- state update: thread -> (urow, uj), c kept in register ---
        float gi = gates_s[urow][0 * HID + uj];
        float gf = gates_s[urow][1 * HID + uj];
        float gg = gates_s[urow][2 * HID + uj];
        float go = gates_s[urow][3 * HID + uj];

        float iv = sigm_f(gi);
        float fv = sigm_f(gf);
        float gv = tanh_f(gg);
        float ov = sigm_f(go);

        c_reg = fmaf(fv, c_reg, iv * gv);
        float hv = ov * tanh_f(c_reg);

        h_s[urow][uj] = hv;
        if (DST != 2) {
            out_seq[t * (B_SZ * HID) + (b0 + urow) * HID + uj] = hv;
        }
        // stage next step's input into the other buffer
        if (xi_act) x_s[par ^ 1][xi_row][xi_k] = x_next;
        __syncthreads();   // h_s + x_s consistent before next step
    }

    if (FINAL) {
        if (tid < ROWS * 2) {
            int r = tid >> 1, o = tid & 1;
            float s = fc_b[o];
            #pragma unroll
            for (int j = 0; j < HID; j++)
                s = fmaf(h_s[r][j], fc_w[o * HID + j], s);
            out_fc[(b0 + r) * 2 + o] = s;
        }
    }
}

extern "C" void kernel_launch(void* const* d_in, const int* in_sizes, int n_in,
                              void* d_out, int out_size)
{
    const float* x    = (const float*)d_in[0];
    const float* Wih0 = (const float*)d_in[1];
    const float* Whh0 = (const float*)d_in[2];
    const float* bih0 = (const float*)d_in[3];
    const float* bhh0 = (const float*)d_in[4];
    const float* Wih1 = (const float*)d_in[5];
    const float* Whh1 = (const float*)d_in[6];
    const float* bih1 = (const float*)d_in[7];
    const float* bhh1 = (const float*)d_in[8];
    const float* Wih2 = (const float*)d_in[9];
    const float* Whh2 = (const float*)d_in[10];
    const float* bih2 = (const float*)d_in[11];
    const float* bhh2 = (const float*)d_in[12];
    const float* fc_w = (const float*)d_in[13];
    const float* fc_b = (const float*)d_in[14];
    float* out = (float*)d_out;

    lstm_layer_kernel<4, 2, 0, false><<<NCTA, NTHR>>>(
        x, Wih0, Whh0, bih0, bhh0, nullptr, nullptr, nullptr);
    lstm_layer_kernel<HID, 0, 1, false><<<NCTA, NTHR>>>(
        nullptr, Wih1, Whh1, bih1, bhh1, nullptr, nullptr, nullptr);
    lstm_layer_kernel<HID, 1, 2, true><<<NCTA, NTHR>>>(
        nullptr, Wih2, Whh2, bih2, bhh2, fc_w, fc_b, out);
}